// round 11
// baseline (speedup 1.0000x reference)
#include <cuda_runtime.h>
#include <cstdint>

#define Bc 4
#define Cc 64
#define Hc 128
#define Wc 128
#define Oc 64
#define Hp 130
#define Wp 130

// Device scratch (no allocation allowed)
__device__ float g_xp[Bc * Hp * Wp * Cc];   // padded NHWC x (~16.5 MiB)
__device__ float g_wb2[9 * 32 * 64];        // stage-2 B: [tap q][n 32][c 64] swizzled tf32
__device__ float g_wb5[9 * 64 * 64];        // stage-5 B: [sample n][o 64][c 64] swizzled tf32

__device__ __forceinline__ float to_tf32(float x) {
    float r; asm("cvt.rna.tf32.f32 %0, %1;" : "=f"(r) : "f"(x)); return r;
}
__device__ __forceinline__ uint32_t smem_u32(const void* p) {
    uint32_t a;
    asm("{ .reg .u64 t; cvta.to.shared.u64 t, %1; cvt.u32.u64 %0, t; }" : "=r"(a) : "l"(p));
    return a;
}
__device__ __forceinline__ void cp16(uint32_t dst, const void* src) {
    asm volatile("cp.async.ca.shared.global [%0], [%1], 16;" :: "r"(dst), "l"(src));
}

// m16n8k8 tf32 MMA
__device__ __forceinline__ void mma8(float* c, const uint32_t* a, uint32_t b0, uint32_t b1) {
    asm volatile("mma.sync.aligned.m16n8k8.row.col.f32.tf32.tf32.f32 "
        "{%0,%1,%2,%3}, {%4,%5,%6,%7}, {%8,%9}, {%0,%1,%2,%3};"
        : "+f"(c[0]), "+f"(c[1]), "+f"(c[2]), "+f"(c[3])
        : "r"(a[0]), "r"(a[1]), "r"(a[2]), "r"(a[3]), "r"(b0), "r"(b1));
}

// smem layout (bytes). Lifetime overlays:
//   [SM_A,  +33536): A row tile / C2,C5 staging
//   [SM_B2, +24576): stage-2 B tiles (3x8KB)  -> then swt(18432)+sidx(4608)
//   [SM_B5, +16384): stage-5 B tile
#define SM_A     0
#define SM_B2    33536
#define SM_SWT   33536
#define SM_SIDX  51968
#define SM_B5    58112
#define SM_TOTAL 74496

// ---------------------------------------------------------------------------
// Fused prep: border zero + weight transposes + NCHW->NHWC transpose
// ---------------------------------------------------------------------------
__global__ __launch_bounds__(256) void prep_kernel(
    const float* __restrict__ x,
    const float* __restrict__ wp,
    const float* __restrict__ wm,
    const float* __restrict__ wc) {
    if (blockIdx.x < 516) {
        int i = blockIdx.x * 256 + threadIdx.x;
        const int per = (2 * 130 + 2 * 128) * 64;  // 33024
        if (i < Bc * per) {
            int b = i / per, r = i % per;
            int base = b * Hp * Wp * Cc;
            if (r < 130 * 64)            g_xp[base + r] = 0.f;
            else if (r < 2 * 130 * 64)   g_xp[base + 129 * Wp * Cc + (r - 130 * 64)] = 0.f;
            else {
                int t = r - 2 * 130 * 64;
                int which = t / (128 * 64);
                int u = t % (128 * 64);
                int rr = u / 64, c = u % 64;
                int w = which ? 129 : 0;
                g_xp[base + (rr + 1) * Wp * Cc + w * Cc + c] = 0.f;
            }
        }
        if (i < 9 * 32 * 64) {
            int q = i >> 11, rem = i & 2047, n = rem >> 6, c = rem & 63;
            float v = 0.f;
            if (n < 18)      v = wp[n * 576 + c * 9 + q];
            else if (n < 27) v = wm[(n - 18) * 576 + c * 9 + q];
            g_wb2[q * 2048 + n * 64 + (c ^ ((n & 7) << 2))] = to_tf32(v);
        }
        if (i < 9 * 64 * 64) {
            int n = i >> 12, rem = i & 4095, o = rem >> 6, c = rem & 63;
            g_wb5[n * 4096 + o * 64 + (c ^ ((o & 7) << 2))] = to_tf32(wc[o * 576 + c * 9 + n]);
        }
    } else {
        int bid = blockIdx.x - 516;
        int wblk = bid & 3, h = (bid >> 2) & 127, z = bid >> 9;
        int b = z >> 1, cblk = z & 1;
        __shared__ float tile[32][33];
        int l = threadIdx.x;
        int tx = l & 31, ty = l >> 5;
        #pragma unroll
        for (int r = 0; r < 4; r++) {
            int c = ty + r * 8;
            tile[c][tx] = x[((b * Cc + cblk * 32 + c) * Hc + h) * Wc + wblk * 32 + tx];
        }
        __syncthreads();
        int j = l & 7, w2 = l >> 3;
        float4 v;
        v.x = tile[j * 4 + 0][w2];
        v.y = tile[j * 4 + 1][w2];
        v.z = tile[j * 4 + 2][w2];
        v.w = tile[j * 4 + 3][w2];
        *(float4*)(g_xp + ((b * Hp + (h + 1)) * Wp + (wblk * 32 + w2 + 1)) * Cc
                   + cblk * 32 + j * 4) = v;
    }
}

// ---------------------------------------------------------------------------
// Main fused kernel: 1 block = one (b,h) row of 128 pixels, 256 threads
// Warp tiling: mg = warp>>1 (32 px), nh = warp&1 (N-half)
// ---------------------------------------------------------------------------
__global__ __launch_bounds__(256, 3) void deform_kernel(
    const float* __restrict__ bp, const float* __restrict__ bm,
    float* __restrict__ out) {

    extern __shared__ char sm[];
    float*    As   = (float*)(sm + SM_A);
    uint32_t* AsU  = (uint32_t*)(sm + SM_A);
    uint32_t* B2U  = (uint32_t*)(sm + SM_B2);
    uint32_t* B5U  = (uint32_t*)(sm + SM_B5);
    float4*   swt4 = (float4*)(sm + SM_SWT);
    int*      sidx = (int*)(sm + SM_SIDX);
    float*    Cst  = (float*)(sm + SM_A);   // staging overlay

    const uint32_t smbA  = smem_u32(sm) + SM_A;
    const uint32_t smbB2 = smem_u32(sm) + SM_B2;
    const uint32_t smbB5 = smem_u32(sm) + SM_B5;
    const int tid = threadIdx.x;
    const int warp = tid >> 5, lane = tid & 31;
    const int g = lane >> 2, t4 = lane & 3;
    const int mg = warp >> 1, nh = warp & 1;
    const int px0 = mg * 32;
    const int h = blockIdx.x, b = blockIdx.y;
    const float* __restrict__ xpb = g_xp + b * (Hp * Wp * Cc);

    // ================= Stage 2: offset/mod conv GEMM (M=128,N=32,K=9x64) =====
    float C2[2][2][4];
    #pragma unroll
    for (int mt = 0; mt < 2; mt++)
        #pragma unroll
        for (int nt = 0; nt < 2; nt++)
            #pragma unroll
            for (int r = 0; r < 4; r++) C2[mt][nt][r] = 0.f;

    for (int qy = 0; qy < 3; qy++) {
        const float* src = xpb + (h + qy) * Wp * Cc;
        // A row: 130 x 64 floats = 2080 float4
        #pragma unroll
        for (int r = 0; r < 9; r++) {
            int f = r * 256 + tid;
            if (f < 2080) {
                int px = f >> 4, cg = f & 15;
                cp16(smbA + (px * 64 + 4 * (cg ^ (px & 7))) * 4, src + px * 64 + cg * 4);
            }
        }
        // 3 B tiles (q = qy*3 + 0..2): 1536 float4
        #pragma unroll
        for (int r = 0; r < 6; r++) {
            int f = r * 256 + tid;
            cp16(smbB2 + f * 16, g_wb2 + qy * 3 * 2048 + f * 4);
        }
        asm volatile("cp.async.commit_group;");
        asm volatile("cp.async.wait_group 0;");
        __syncthreads();
        #pragma unroll
        for (int qx = 0; qx < 3; qx++) {
            const int gq = (g + qx) & 7;
            #pragma unroll
            for (int ks = 0; ks < 8; ks++) {
                const int k0 = ks * 8;
                const int sa0 = (k0 + t4) ^ (gq << 2);
                const int sa1 = (k0 + t4 + 4) ^ (gq << 2);
                const int sb0 = (k0 + t4) ^ (g << 2);
                const int sb1 = (k0 + t4 + 4) ^ (g << 2);
                uint32_t bb[4];
                #pragma unroll
                for (int nt = 0; nt < 2; nt++) {
                    int n = (nh * 2 + nt) * 8 + g;
                    bb[nt * 2]     = B2U[qx * 2048 + n * 64 + sb0];
                    bb[nt * 2 + 1] = B2U[qx * 2048 + n * 64 + sb1];
                }
                #pragma unroll
                for (int mt = 0; mt < 2; mt++) {
                    uint32_t a[4];
                    int r0 = px0 + mt * 16 + g + qx;
                    a[0] = AsU[r0 * 64 + sa0];
                    a[1] = AsU[(r0 + 8) * 64 + sa0];
                    a[2] = AsU[r0 * 64 + sa1];
                    a[3] = AsU[(r0 + 8) * 64 + sa1];
                    #pragma unroll
                    for (int nt = 0; nt < 2; nt++)
                        mma8(C2[mt][nt], a, bb[nt * 2], bb[nt * 2 + 1]);
                }
            }
        }
        __syncthreads();
    }
    // stage C2 -> smem [n][132 stride]  (A-region overlay)
    #pragma unroll
    for (int mt = 0; mt < 2; mt++)
        #pragma unroll
        for (int nt = 0; nt < 2; nt++) {
            int n = (nh * 2 + nt) * 8 + 2 * t4;
            int px = px0 + mt * 16 + g;
            if (n < 27)     { Cst[n * 132 + px]       = C2[mt][nt][0];
                              Cst[n * 132 + px + 8]   = C2[mt][nt][2]; }
            if (n + 1 < 27) { Cst[(n + 1) * 132 + px]     = C2[mt][nt][1];
                              Cst[(n + 1) * 132 + px + 8] = C2[mt][nt][3]; }
        }
    __syncthreads();

    // ============ Offsets epilogue (writes tables into dead B2 region) ========
    for (int task = tid; task < 1152; task += 256) {
        int px = task / 9, n = task - px * 9;
        float offx = Cst[n * 132 + px]        + bp[n];
        float offy = Cst[(9 + n) * 132 + px]  + bp[9 + n];
        float mz   = Cst[(18 + n) * 132 + px] + bm[n];
        float mm = 1.0f / (1.0f + __expf(-mz));
        int i = n / 3, jj = n % 3;
        float p_x = (float)(h + i) + offx;
        float p_y = (float)(px + jj) + offy;
        float fx = floorf(p_x), fy = floorf(p_y);
        float qltx = fminf(fmaxf(fx,       0.f), 129.f);
        float qlty = fminf(fmaxf(fy,       0.f), 129.f);
        float qrbx = fminf(fmaxf(fx + 1.f, 0.f), 129.f);
        float qrby = fminf(fmaxf(fy + 1.f, 0.f), 129.f);
        float pcx  = fminf(fmaxf(p_x, 0.f), 129.f);
        float pcy  = fminf(fmaxf(p_y, 0.f), 129.f);
        float glt = (1.f + (qltx - pcx)) * (1.f + (qlty - pcy));
        float grb = (1.f - (qrbx - pcx)) * (1.f - (qrby - pcy));
        float glb = (1.f + (qltx - pcx)) * (1.f - (qrby - pcy));
        float grt = (1.f - (qrbx - pcx)) * (1.f + (qlty - pcy));
        int iltx = (int)qltx, ilty = (int)qlty;
        int irbx = (int)qrbx, irby = (int)qrby;
        int base = (iltx * Wp + ilty) * Cc;
        int pack = base | ((irbx - iltx) << 24) | ((irby - ilty) << 25);
        float4 wv;
        wv.x = glt * mm; wv.y = grb * mm; wv.z = glb * mm; wv.w = grt * mm;
        sidx[px * 9 + n] = pack;
        swt4[px * 9 + n] = wv;
    }
    __syncthreads();

    // ============ Stage 5: sample + GEMM (M=128,N=64,K=9x64) ============
    float C5[2][4][4];
    #pragma unroll
    for (int mt = 0; mt < 2; mt++)
        #pragma unroll
        for (int nt = 0; nt < 4; nt++)
            #pragma unroll
            for (int r = 0; r < 4; r++) C5[mt][nt][r] = 0.f;

    const int n0 = nh * 32;
    const int half = lane >> 4;        // which px of the pair
    const int c4 = (lane & 15) * 4;    // channel quad
    for (int n = 0; n < 9; n++) {
        // B tile via cp.async (overlaps with sampling LDGs)
        #pragma unroll
        for (int r = 0; r < 4; r++) {
            int f = r * 256 + tid;
            cp16(smbB5 + f * 16, g_wb5 + n * 4096 + f * 4);
        }
        asm volatile("cp.async.commit_group;");
        // A tile: float4 bilinear samples (2 px per warp-iteration)
        #pragma unroll
        for (int k = 0; k < 8; k++) {
            int px = warp * 16 + k * 2 + half;
            int si = sidx[px * 9 + n];
            float4 w4 = swt4[px * 9 + n];
            int base = (si & 0xFFFFFF) + c4;
            int dx = (si & (1 << 24)) ? (Wp * Cc) : 0;
            int dy = (si & (1 << 25)) ? Cc : 0;
            float4 t0 = *(const float4*)(xpb + base);
            float4 t1 = *(const float4*)(xpb + base + dx + dy);
            float4 t2 = *(const float4*)(xpb + base + dy);
            float4 t3 = *(const float4*)(xpb + base + dx);
            float4 v;
            v.x = to_tf32(w4.x * t0.x + w4.y * t1.x + w4.z * t2.x + w4.w * t3.x);
            v.y = to_tf32(w4.x * t0.y + w4.y * t1.y + w4.z * t2.y + w4.w * t3.y);
            v.z = to_tf32(w4.x * t0.z + w4.y * t1.z + w4.z * t2.z + w4.w * t3.z);
            v.w = to_tf32(w4.x * t0.w + w4.y * t1.w + w4.z * t2.w + w4.w * t3.w);
            *(float4*)(As + px * 64 + (c4 ^ ((px & 7) << 2))) = v;
        }
        asm volatile("cp.async.wait_group 0;");
        __syncthreads();
        #pragma unroll
        for (int ks = 0; ks < 8; ks++) {
            const int k0 = ks * 8;
            const int sc0 = (k0 + t4) ^ (g << 2);
            const int sc1 = (k0 + t4 + 4) ^ (g << 2);
            uint32_t bb[8];
            #pragma unroll
            for (int nt = 0; nt < 4; nt++) {
                int nn = n0 + nt * 8 + g;
                bb[nt * 2]     = B5U[nn * 64 + sc0];
                bb[nt * 2 + 1] = B5U[nn * 64 + sc1];
            }
            #pragma unroll
            for (int mt = 0; mt < 2; mt++) {
                uint32_t a[4];
                int r0 = px0 + mt * 16 + g;
                a[0] = AsU[r0 * 64 + sc0];
                a[1] = AsU[(r0 + 8) * 64 + sc0];
                a[2] = AsU[r0 * 64 + sc1];
                a[3] = AsU[(r0 + 8) * 64 + sc1];
                #pragma unroll
                for (int nt = 0; nt < 4; nt++)
                    mma8(C5[mt][nt], a, bb[nt * 2], bb[nt * 2 + 1]);
            }
        }
        __syncthreads();
    }

    // stage C5 -> smem [o][128 stride]
    #pragma unroll
    for (int mt = 0; mt < 2; mt++)
        #pragma unroll
        for (int nt = 0; nt < 4; nt++) {
            int o = n0 + nt * 8 + 2 * t4;
            int px = px0 + mt * 16 + g;
            Cst[o * 128 + px]           = C5[mt][nt][0];
            Cst[(o + 1) * 128 + px]     = C5[mt][nt][1];
            Cst[o * 128 + px + 8]       = C5[mt][nt][2];
            Cst[(o + 1) * 128 + px + 8] = C5[mt][nt][3];
        }
    __syncthreads();

    // coalesced NCHW store
    float* __restrict__ ob = out + (b * Oc * Hc + h) * Wc;
    #pragma unroll
    for (int r = 0; r < 32; r++) {
        int f = r * 256 + tid;
        int o = f >> 7, px = f & 127;
        ob[o * (Hc * Wc) + px] = Cst[o * 128 + px];
    }
}

// ---------------------------------------------------------------------------
extern "C" void kernel_launch(void* const* d_in, const int* in_sizes, int n_in,
                              void* d_out, int out_size) {
    const float* x      = (const float*)d_in[0];
    const float* w_p    = (const float*)d_in[1];
    const float* b_p    = (const float*)d_in[2];
    const float* w_m    = (const float*)d_in[3];
    const float* b_m    = (const float*)d_in[4];
    const float* w_conv = (const float*)d_in[5];
    float* out = (float*)d_out;

    cudaFuncSetAttribute(deform_kernel,
                         cudaFuncAttributeMaxDynamicSharedMemorySize, SM_TOTAL);

    prep_kernel<<<516 + 4096, 256>>>(x, w_p, w_m, w_conv);
    deform_kernel<<<dim3(Hc, Bc), 256, SM_TOTAL>>>(b_p, b_m, out);
}

// round 12
// speedup vs baseline: 1.0226x; 1.0226x over previous
#include <cuda_runtime.h>
#include <cuda_fp16.h>
#include <cstdint>

#define Bc 4
#define Cc 64
#define Hc 128
#define Wc 128
#define Oc 64
#define Hp 130
#define Wp 130

// Device scratch (no allocation allowed)
__device__ float g_xp[Bc * Hp * Wp * Cc];   // padded NHWC x (~16.5 MiB)
__device__ float g_wb2[9 * 32 * 64];        // stage-2 B: [tap q][n 32][c 64] swizzled tf32
__device__ float g_wb5[9 * 64 * 64];        // stage-5 B: [sample n][o 64][c 64] swizzled tf32

__device__ __forceinline__ float to_tf32(float x) {
    float r; asm("cvt.rna.tf32.f32 %0, %1;" : "=f"(r) : "f"(x)); return r;
}
__device__ __forceinline__ uint32_t smem_u32(const void* p) {
    uint32_t a;
    asm("{ .reg .u64 t; cvta.to.shared.u64 t, %1; cvt.u32.u64 %0, t; }" : "=r"(a) : "l"(p));
    return a;
}
__device__ __forceinline__ void cp16(uint32_t dst, const void* src) {
    asm volatile("cp.async.ca.shared.global [%0], [%1], 16;" :: "r"(dst), "l"(src));
}

// m16n8k8 tf32 MMA
__device__ __forceinline__ void mma8(float* c, const uint32_t* a, uint32_t b0, uint32_t b1) {
    asm volatile("mma.sync.aligned.m16n8k8.row.col.f32.tf32.tf32.f32 "
        "{%0,%1,%2,%3}, {%4,%5,%6,%7}, {%8,%9}, {%0,%1,%2,%3};"
        : "+f"(c[0]), "+f"(c[1]), "+f"(c[2]), "+f"(c[3])
        : "r"(a[0]), "r"(a[1]), "r"(a[2]), "r"(a[3]), "r"(b0), "r"(b1));
}

// smem layout (bytes). Lifetime overlays:
//   [SM_A0,+33536): stage-2 A row (33280) / stage-5 A buf0 (32768) / C staging
//   [SM_A1,+32768): stage-5 A buf1 ; stage-2 B tiles (24576) overlay
//   [SM_B50/B51,+16384 each): stage-5 B double buffer
//   tables: swt half4 (9216) + sidx (4608)
#define SM_A0    0
#define SM_A1    33536
#define SM_B2    33536
#define SM_B50   66304
#define SM_B51   82688
#define SM_SWT   99072
#define SM_SIDX  108288
#define SM_TOTAL 112896

// ---------------------------------------------------------------------------
// Fused prep: border zero + weight transposes + NCHW->NHWC transpose
// ---------------------------------------------------------------------------
__global__ __launch_bounds__(256) void prep_kernel(
    const float* __restrict__ x,
    const float* __restrict__ wp,
    const float* __restrict__ wm,
    const float* __restrict__ wc) {
    if (blockIdx.x < 516) {
        int i = blockIdx.x * 256 + threadIdx.x;
        const int per = (2 * 130 + 2 * 128) * 64;  // 33024
        if (i < Bc * per) {
            int b = i / per, r = i % per;
            int base = b * Hp * Wp * Cc;
            if (r < 130 * 64)            g_xp[base + r] = 0.f;
            else if (r < 2 * 130 * 64)   g_xp[base + 129 * Wp * Cc + (r - 130 * 64)] = 0.f;
            else {
                int t = r - 2 * 130 * 64;
                int which = t / (128 * 64);
                int u = t % (128 * 64);
                int rr = u / 64, c = u % 64;
                int w = which ? 129 : 0;
                g_xp[base + (rr + 1) * Wp * Cc + w * Cc + c] = 0.f;
            }
        }
        if (i < 9 * 32 * 64) {
            int q = i >> 11, rem = i & 2047, n = rem >> 6, c = rem & 63;
            float v = 0.f;
            if (n < 18)      v = wp[n * 576 + c * 9 + q];
            else if (n < 27) v = wm[(n - 18) * 576 + c * 9 + q];
            g_wb2[q * 2048 + n * 64 + (c ^ ((n & 7) << 2))] = to_tf32(v);
        }
        if (i < 9 * 64 * 64) {
            int n = i >> 12, rem = i & 4095, o = rem >> 6, c = rem & 63;
            g_wb5[n * 4096 + o * 64 + (c ^ ((o & 7) << 2))] = to_tf32(wc[o * 576 + c * 9 + n]);
        }
    } else {
        int bid = blockIdx.x - 516;
        int wblk = bid & 3, h = (bid >> 2) & 127, z = bid >> 9;
        int b = z >> 1, cblk = z & 1;
        __shared__ float tile[32][33];
        int l = threadIdx.x;
        int tx = l & 31, ty = l >> 5;
        #pragma unroll
        for (int r = 0; r < 4; r++) {
            int c = ty + r * 8;
            tile[c][tx] = x[((b * Cc + cblk * 32 + c) * Hc + h) * Wc + wblk * 32 + tx];
        }
        __syncthreads();
        int j = l & 7, w2 = l >> 3;
        float4 v;
        v.x = tile[j * 4 + 0][w2];
        v.y = tile[j * 4 + 1][w2];
        v.z = tile[j * 4 + 2][w2];
        v.w = tile[j * 4 + 3][w2];
        *(float4*)(g_xp + ((b * Hp + (h + 1)) * Wp + (wblk * 32 + w2 + 1)) * Cc
                   + cblk * 32 + j * 4) = v;
    }
}

// ---------------------------------------------------------------------------
// Main fused kernel: 1 block = one (b,h) row of 128 pixels, 256 threads
// Warp tiling: mg = warp>>1 (32 px), nh = warp&1 (N-half)
// ---------------------------------------------------------------------------
__global__ __launch_bounds__(256, 2) void deform_kernel(
    const float* __restrict__ bp, const float* __restrict__ bm,
    float* __restrict__ out) {

    extern __shared__ char sm[];
    float*    As0  = (float*)(sm + SM_A0);
    float*    As1  = (float*)(sm + SM_A1);
    uint32_t* A0U  = (uint32_t*)(sm + SM_A0);
    uint32_t* A1U  = (uint32_t*)(sm + SM_A1);
    uint32_t* B2U  = (uint32_t*)(sm + SM_B2);
    uint32_t* B50U = (uint32_t*)(sm + SM_B50);
    uint32_t* B51U = (uint32_t*)(sm + SM_B51);
    uint2*    swtH = (uint2*)(sm + SM_SWT);
    int*      sidx = (int*)(sm + SM_SIDX);
    float*    Cst  = (float*)(sm + SM_A0);   // staging overlay

    const uint32_t smbA0  = smem_u32(sm) + SM_A0;
    const uint32_t smbB2  = smem_u32(sm) + SM_B2;
    const uint32_t smbB50 = smem_u32(sm) + SM_B50;
    const uint32_t smbB51 = smem_u32(sm) + SM_B51;
    const int tid = threadIdx.x;
    const int warp = tid >> 5, lane = tid & 31;
    const int g = lane >> 2, t4 = lane & 3;
    const int mg = warp >> 1, nh = warp & 1;
    const int px0 = mg * 32;
    const int h = blockIdx.x, b = blockIdx.y;
    const float* __restrict__ xpb = g_xp + b * (Hp * Wp * Cc);

    // ================= Stage 2: offset/mod conv GEMM (M=128,N=32,K=9x64) =====
    float C2[2][2][4];
    #pragma unroll
    for (int mt = 0; mt < 2; mt++)
        #pragma unroll
        for (int nt = 0; nt < 2; nt++)
            #pragma unroll
            for (int r = 0; r < 4; r++) C2[mt][nt][r] = 0.f;

    for (int qy = 0; qy < 3; qy++) {
        const float* src = xpb + (h + qy) * Wp * Cc;
        // A row: 130 x 64 floats = 2080 float4
        #pragma unroll
        for (int r = 0; r < 9; r++) {
            int f = r * 256 + tid;
            if (f < 2080) {
                int px = f >> 4, cg = f & 15;
                cp16(smbA0 + (px * 64 + 4 * (cg ^ (px & 7))) * 4, src + px * 64 + cg * 4);
            }
        }
        // 3 B tiles (q = qy*3 + 0..2): 1536 float4
        #pragma unroll
        for (int r = 0; r < 6; r++) {
            int f = r * 256 + tid;
            cp16(smbB2 + f * 16, g_wb2 + qy * 3 * 2048 + f * 4);
        }
        asm volatile("cp.async.commit_group;");
        asm volatile("cp.async.wait_group 0;");
        __syncthreads();
        #pragma unroll
        for (int qx = 0; qx < 3; qx++) {
            const int gq = (g + qx) & 7;
            #pragma unroll
            for (int ks = 0; ks < 8; ks++) {
                const int k0 = ks * 8;
                const int sa0 = (k0 + t4) ^ (gq << 2);
                const int sa1 = (k0 + t4 + 4) ^ (gq << 2);
                const int sb0 = (k0 + t4) ^ (g << 2);
                const int sb1 = (k0 + t4 + 4) ^ (g << 2);
                uint32_t bb[4];
                #pragma unroll
                for (int nt = 0; nt < 2; nt++) {
                    int n = (nh * 2 + nt) * 8 + g;
                    bb[nt * 2]     = B2U[qx * 2048 + n * 64 + sb0];
                    bb[nt * 2 + 1] = B2U[qx * 2048 + n * 64 + sb1];
                }
                #pragma unroll
                for (int mt = 0; mt < 2; mt++) {
                    uint32_t a[4];
                    int r0 = px0 + mt * 16 + g + qx;
                    a[0] = A0U[r0 * 64 + sa0];
                    a[1] = A0U[(r0 + 8) * 64 + sa0];
                    a[2] = A0U[r0 * 64 + sa1];
                    a[3] = A0U[(r0 + 8) * 64 + sa1];
                    #pragma unroll
                    for (int nt = 0; nt < 2; nt++)
                        mma8(C2[mt][nt], a, bb[nt * 2], bb[nt * 2 + 1]);
                }
            }
        }
        __syncthreads();
    }
    // stage C2 -> smem [n][132 stride] (A0 overlay)
    #pragma unroll
    for (int mt = 0; mt < 2; mt++)
        #pragma unroll
        for (int nt = 0; nt < 2; nt++) {
            int n = (nh * 2 + nt) * 8 + 2 * t4;
            int px = px0 + mt * 16 + g;
            if (n < 27)     { Cst[n * 132 + px]       = C2[mt][nt][0];
                              Cst[n * 132 + px + 8]   = C2[mt][nt][2]; }
            if (n + 1 < 27) { Cst[(n + 1) * 132 + px]     = C2[mt][nt][1];
                              Cst[(n + 1) * 132 + px + 8] = C2[mt][nt][3]; }
        }
    __syncthreads();

    // ============ Offsets epilogue: tables (swt as half4) ============
    for (int task = tid; task < 1152; task += 256) {
        int px = task / 9, n = task - px * 9;
        float offx = Cst[n * 132 + px]        + bp[n];
        float offy = Cst[(9 + n) * 132 + px]  + bp[9 + n];
        float mz   = Cst[(18 + n) * 132 + px] + bm[n];
        float mm = 1.0f / (1.0f + __expf(-mz));
        int i = n / 3, jj = n % 3;
        float p_x = (float)(h + i) + offx;
        float p_y = (float)(px + jj) + offy;
        float fx = floorf(p_x), fy = floorf(p_y);
        float qltx = fminf(fmaxf(fx,       0.f), 129.f);
        float qlty = fminf(fmaxf(fy,       0.f), 129.f);
        float qrbx = fminf(fmaxf(fx + 1.f, 0.f), 129.f);
        float qrby = fminf(fmaxf(fy + 1.f, 0.f), 129.f);
        float pcx  = fminf(fmaxf(p_x, 0.f), 129.f);
        float pcy  = fminf(fmaxf(p_y, 0.f), 129.f);
        float glt = (1.f + (qltx - pcx)) * (1.f + (qlty - pcy));
        float grb = (1.f - (qrbx - pcx)) * (1.f - (qrby - pcy));
        float glb = (1.f + (qltx - pcx)) * (1.f - (qrby - pcy));
        float grt = (1.f - (qrbx - pcx)) * (1.f + (qlty - pcy));
        int iltx = (int)qltx, ilty = (int)qlty;
        int irbx = (int)qrbx, irby = (int)qrby;
        int base = (iltx * Wp + ilty) * Cc;
        int pack = base | ((irbx - iltx) << 24) | ((irby - ilty) << 25);
        __half2 h01 = __floats2half2_rn(glt * mm, grb * mm);
        __half2 h23 = __floats2half2_rn(glb * mm, grt * mm);
        uint2 pk;
        pk.x = *(uint32_t*)&h01;
        pk.y = *(uint32_t*)&h23;
        sidx[px * 9 + n] = pack;
        swtH[px * 9 + n] = pk;
    }
    __syncthreads();

    // ============ Stage 5: pipelined sample + GEMM (M=128,N=64,K=9x64) =======
    float C5[2][4][4];
    #pragma unroll
    for (int mt = 0; mt < 2; mt++)
        #pragma unroll
        for (int nt = 0; nt < 4; nt++)
            #pragma unroll
            for (int r = 0; r < 4; r++) C5[mt][nt][r] = 0.f;

    const int n0 = nh * 32;
    const int half_ = lane >> 4;       // which px of the pair
    const int c4 = (lane & 15) * 4;    // channel quad

    auto issueB = [&](int n, uint32_t dstB) {
        #pragma unroll
        for (int r = 0; r < 4; r++) {
            int f = r * 256 + tid;
            cp16(dstB + f * 16, g_wb5 + n * 4096 + f * 4);
        }
        asm volatile("cp.async.commit_group;");
    };
    auto sample_chunk = [&](int n, float* Adst) {
        #pragma unroll
        for (int k = 0; k < 8; k++) {
            int px = warp * 16 + k * 2 + half_;
            int si = sidx[px * 9 + n];
            uint2 pk = swtH[px * 9 + n];
            float2 w01 = __half22float2(*(__half2*)&pk.x);
            float2 w23 = __half22float2(*(__half2*)&pk.y);
            int base = (si & 0xFFFFFF) + c4;
            int dx = (si & (1 << 24)) ? (Wp * Cc) : 0;
            int dy = (si & (1 << 25)) ? Cc : 0;
            float4 t0 = *(const float4*)(xpb + base);
            float4 t1 = *(const float4*)(xpb + base + dx + dy);
            float4 t2 = *(const float4*)(xpb + base + dy);
            float4 t3 = *(const float4*)(xpb + base + dx);
            float4 v;
            v.x = to_tf32(w01.x * t0.x + w01.y * t1.x + w23.x * t2.x + w23.y * t3.x);
            v.y = to_tf32(w01.x * t0.y + w01.y * t1.y + w23.x * t2.y + w23.y * t3.y);
            v.z = to_tf32(w01.x * t0.z + w01.y * t1.z + w23.x * t2.z + w23.y * t3.z);
            v.w = to_tf32(w01.x * t0.w + w01.y * t1.w + w23.x * t2.w + w23.y * t3.w);
            *(float4*)(Adst + px * 64 + (c4 ^ ((px & 7) << 2))) = v;
        }
    };

    // prologue: B(0) + samples(0) into buf0
    issueB(0, smbB50);
    sample_chunk(0, As0);
    asm volatile("cp.async.wait_group 0;");
    __syncthreads();

    for (int n = 0; n < 9; n++) {
        uint32_t* Au = (n & 1) ? A1U : A0U;
        uint32_t* Bu = (n & 1) ? B51U : B50U;
        if (n < 8) issueB(n + 1, (n & 1) ? smbB50 : smbB51);
        // MMA(n)
        #pragma unroll
        for (int ks = 0; ks < 8; ks++) {
            const int k0 = ks * 8;
            const int sc0 = (k0 + t4) ^ (g << 2);
            const int sc1 = (k0 + t4 + 4) ^ (g << 2);
            uint32_t bb[8];
            #pragma unroll
            for (int nt = 0; nt < 4; nt++) {
                int nn = n0 + nt * 8 + g;
                bb[nt * 2]     = Bu[nn * 64 + sc0];
                bb[nt * 2 + 1] = Bu[nn * 64 + sc1];
            }
            #pragma unroll
            for (int mt = 0; mt < 2; mt++) {
                uint32_t a[4];
                int r0 = px0 + mt * 16 + g;
                a[0] = Au[r0 * 64 + sc0];
                a[1] = Au[(r0 + 8) * 64 + sc0];
                a[2] = Au[r0 * 64 + sc1];
                a[3] = Au[(r0 + 8) * 64 + sc1];
                #pragma unroll
                for (int nt = 0; nt < 4; nt++)
                    mma8(C5[mt][nt], a, bb[nt * 2], bb[nt * 2 + 1]);
            }
        }
        // sample(n+1) into the other A buffer, overlapped with other warps' MMA
        if (n < 8) {
            sample_chunk(n + 1, (n & 1) ? As0 : As1);
            asm volatile("cp.async.wait_group 0;");
        }
        __syncthreads();
    }

    // stage C5 -> smem [o][128 stride] (A0 overlay)
    #pragma unroll
    for (int mt = 0; mt < 2; mt++)
        #pragma unroll
        for (int nt = 0; nt < 4; nt++) {
            int o = n0 + nt * 8 + 2 * t4;
            int px = px0 + mt * 16 + g;
            Cst[o * 128 + px]           = C5[mt][nt][0];
            Cst[(o + 1) * 128 + px]     = C5[mt][nt][1];
            Cst[o * 128 + px + 8]       = C5[mt][nt][2];
            Cst[(o + 1) * 128 + px + 8] = C5[mt][nt][3];
        }
    __syncthreads();

    // coalesced NCHW store
    float* __restrict__ ob = out + (b * Oc * Hc + h) * Wc;
    #pragma unroll
    for (int r = 0; r < 32; r++) {
        int f = r * 256 + tid;
        int o = f >> 7, px = f & 127;
        ob[o * (Hc * Wc) + px] = Cst[o * 128 + px];
    }
}

// ---------------------------------------------------------------------------
extern "C" void kernel_launch(void* const* d_in, const int* in_sizes, int n_in,
                              void* d_out, int out_size) {
    const float* x      = (const float*)d_in[0];
    const float* w_p    = (const float*)d_in[1];
    const float* b_p    = (const float*)d_in[2];
    const float* w_m    = (const float*)d_in[3];
    const float* b_m    = (const float*)d_in[4];
    const float* w_conv = (const float*)d_in[5];
    float* out = (float*)d_out;

    cudaFuncSetAttribute(deform_kernel,
                         cudaFuncAttributeMaxDynamicSharedMemorySize, SM_TOTAL);

    prep_kernel<<<516 + 4096, 256>>>(x, w_p, w_m, w_conv);
    deform_kernel<<<dim3(Hc, Bc), 256, SM_TOTAL>>>(b_p, b_m, out);
}

// round 14
// speedup vs baseline: 1.5192x; 1.4856x over previous
#include <cuda_runtime.h>
#include <cuda_fp16.h>
#include <cstdint>

#define Bc 4
#define Cc 64
#define Hc 128
#define Wc 128
#define Oc 64
#define Hp 130
#define Wp 130

// Device scratch (no allocation allowed)
__device__ __half   g_xph[Bc * Hp * Wp * Cc];  // padded NHWC x, fp16 (~8.3 MiB)
__device__ uint32_t g_wb2h[9 * 32 * 32];       // stage-2 B: [q][n 32][u 32] half2, swizzled
__device__ uint32_t g_wb5h[9 * 64 * 32];       // stage-5 B: [n][o 64][u 32] half2, swizzled

__device__ __forceinline__ uint32_t smem_u32(const void* p) {
    uint32_t a;
    asm("{ .reg .u64 t; cvta.to.shared.u64 t, %1; cvt.u32.u64 %0, t; }" : "=r"(a) : "l"(p));
    return a;
}
__device__ __forceinline__ void cp16(uint32_t dst, const void* src) {
    asm volatile("cp.async.ca.shared.global [%0], [%1], 16;" :: "r"(dst), "l"(src));
}

// m16n8k16 fp16 MMA, fp32 accumulate
__device__ __forceinline__ void mma16(float* c, const uint32_t* a, uint32_t b0, uint32_t b1) {
    asm volatile("mma.sync.aligned.m16n8k16.row.col.f32.f16.f16.f32 "
        "{%0,%1,%2,%3}, {%4,%5,%6,%7}, {%8,%9}, {%0,%1,%2,%3};"
        : "+f"(c[0]), "+f"(c[1]), "+f"(c[2]), "+f"(c[3])
        : "r"(a[0]), "r"(a[1]), "r"(a[2]), "r"(a[3]), "r"(b0), "r"(b1));
}

// smem layout (bytes). C5 staging (32.8KB fp32) overlays A+B2+B5 (36.5KB).
#define SM_A     0          /* stage2 A row 130x128B=16640 (pad 16896); stage5 A 16384 */
#define SM_B2    16896      /* 3 x 4096 */
#define SM_B5    29184      /* 8192 (64 o-rows x 128B)  <-- was 4096: R13 bug */
#define SM_SWT   37376      /* uint2[1152] = 9216 */
#define SM_SIDX  46592      /* int[1152] = 4608 */
#define SM_TOTAL 51200

// ---------------------------------------------------------------------------
// Fused prep: border zero + weight transposes (fp16 pack) + NCHW->NHWC fp16
// ---------------------------------------------------------------------------
__global__ __launch_bounds__(256) void prep_kernel(
    const float* __restrict__ x,
    const float* __restrict__ wp,
    const float* __restrict__ wm,
    const float* __restrict__ wc) {
    if (blockIdx.x < 516) {
        int i = blockIdx.x * 256 + threadIdx.x;
        const int per = (2 * 130 + 2 * 128) * 64;  // 33024
        if (i < Bc * per) {
            int b = i / per, r = i % per;
            int base = b * Hp * Wp * Cc;
            __half z = __float2half(0.f);
            if (r < 130 * 64)            g_xph[base + r] = z;
            else if (r < 2 * 130 * 64)   g_xph[base + 129 * Wp * Cc + (r - 130 * 64)] = z;
            else {
                int t = r - 2 * 130 * 64;
                int which = t / (128 * 64);
                int u = t % (128 * 64);
                int rr = u / 64, c = u % 64;
                int w = which ? 129 : 0;
                g_xph[base + (rr + 1) * Wp * Cc + w * Cc + c] = z;
            }
        }
        if (i < 9 * 32 * 32) {
            int q = i >> 10, rem = i & 1023, n = rem >> 5, u = rem & 31;
            int c0 = 2 * u, c1 = 2 * u + 1;
            float v0 = 0.f, v1 = 0.f;
            if (n < 18)      { v0 = wp[n * 576 + c0 * 9 + q]; v1 = wp[n * 576 + c1 * 9 + q]; }
            else if (n < 27) { v0 = wm[(n - 18) * 576 + c0 * 9 + q]; v1 = wm[(n - 18) * 576 + c1 * 9 + q]; }
            __half2 hv = __floats2half2_rn(v0, v1);
            g_wb2h[q * 1024 + n * 32 + (u ^ ((n & 7) << 2))] = *(uint32_t*)&hv;
        }
        if (i < 9 * 64 * 32) {
            int n = i >> 11, rem = i & 2047, o = rem >> 5, u = rem & 31;
            float v0 = wc[o * 576 + (2 * u) * 9 + n];
            float v1 = wc[o * 576 + (2 * u + 1) * 9 + n];
            __half2 hv = __floats2half2_rn(v0, v1);
            g_wb5h[n * 2048 + o * 32 + (u ^ ((o & 7) << 2))] = *(uint32_t*)&hv;
        }
    } else {
        int bid = blockIdx.x - 516;
        int wblk = bid & 3, h = (bid >> 2) & 127, z = bid >> 9;
        int b = z >> 1, cblk = z & 1;
        __shared__ float tile[32][33];
        int l = threadIdx.x;
        int tx = l & 31, ty = l >> 5;
        #pragma unroll
        for (int r = 0; r < 4; r++) {
            int c = ty + r * 8;
            tile[c][tx] = x[((b * Cc + cblk * 32 + c) * Hc + h) * Wc + wblk * 32 + tx];
        }
        __syncthreads();
        int j = l & 7, w2 = l >> 3;
        __half2 h0 = __floats2half2_rn(tile[j * 4 + 0][w2], tile[j * 4 + 1][w2]);
        __half2 h1 = __floats2half2_rn(tile[j * 4 + 2][w2], tile[j * 4 + 3][w2]);
        uint2 v;
        v.x = *(uint32_t*)&h0;
        v.y = *(uint32_t*)&h1;
        *(uint2*)(g_xph + ((b * Hp + (h + 1)) * Wp + (wblk * 32 + w2 + 1)) * Cc
                  + cblk * 32 + j * 4) = v;
    }
}

// ---------------------------------------------------------------------------
// Main fused kernel: 1 block = one (b,h) row of 128 pixels, 256 threads
// Warp tiling: mg = warp>>1 (32 px), nh = warp&1 (N-half)
// ---------------------------------------------------------------------------
__global__ __launch_bounds__(256, 2) void deform_kernel(
    const float* __restrict__ bp, const float* __restrict__ bm,
    float* __restrict__ out) {

    extern __shared__ char sm[];
    uint32_t* AsU  = (uint32_t*)(sm + SM_A);   // half2-unit view
    uint32_t* B2U  = (uint32_t*)(sm + SM_B2);
    uint32_t* B5U  = (uint32_t*)(sm + SM_B5);
    uint2*    swtH = (uint2*)(sm + SM_SWT);
    int*      sidx = (int*)(sm + SM_SIDX);
    float*    Cst  = (float*)(sm + SM_A);      // fp32 staging overlay

    const uint32_t smbA  = smem_u32(sm) + SM_A;
    const uint32_t smbB2 = smem_u32(sm) + SM_B2;
    const uint32_t smbB5 = smem_u32(sm) + SM_B5;
    const int tid = threadIdx.x;
    const int warp = tid >> 5, lane = tid & 31;
    const int g = lane >> 2, t4 = lane & 3;
    const int mg = warp >> 1, nh = warp & 1;
    const int px0 = mg * 32;
    const int h = blockIdx.x, b = blockIdx.y;
    const __half* __restrict__ xpb = g_xph + b * (Hp * Wp * Cc);

    // ================= Stage 2: offset/mod conv GEMM (M=128,N=32,K=9x64) =====
    float C2[2][2][4];
    #pragma unroll
    for (int mt = 0; mt < 2; mt++)
        #pragma unroll
        for (int nt = 0; nt < 2; nt++)
            #pragma unroll
            for (int r = 0; r < 4; r++) C2[mt][nt][r] = 0.f;

    for (int qy = 0; qy < 3; qy++) {
        const __half* src = xpb + (h + qy) * Wp * Cc;
        // A row: 130 px x 128B = 1040 x 16B, raw fp16 (no cvt needed)
        #pragma unroll
        for (int r = 0; r < 5; r++) {
            int f = r * 256 + tid;
            if (f < 1040) {
                int px = f >> 3, ug = f & 7;
                cp16(smbA + px * 128 + ((ug ^ (px & 7)) << 4), src + px * 64 + ug * 8);
            }
        }
        // 3 B tiles: 768 x 16B
        #pragma unroll
        for (int r = 0; r < 3; r++) {
            int f = r * 256 + tid;
            cp16(smbB2 + f * 16, g_wb2h + qy * 3 * 1024 + f * 4);
        }
        asm volatile("cp.async.commit_group;");
        asm volatile("cp.async.wait_group 0;");
        __syncthreads();
        #pragma unroll
        for (int qx = 0; qx < 3; qx++) {
            const int gq = (g + qx) & 7;
            #pragma unroll
            for (int ks = 0; ks < 4; ks++) {
                const int k0 = ks * 8;
                const int sa0 = (k0 + t4) ^ (gq << 2);
                const int sa1 = (k0 + t4 + 4) ^ (gq << 2);
                const int sb0 = (k0 + t4) ^ (g << 2);
                const int sb1 = (k0 + t4 + 4) ^ (g << 2);
                uint32_t bb[4];
                #pragma unroll
                for (int nt = 0; nt < 2; nt++) {
                    int n = (nh * 2 + nt) * 8 + g;
                    bb[nt * 2]     = B2U[qx * 1024 + n * 32 + sb0];
                    bb[nt * 2 + 1] = B2U[qx * 1024 + n * 32 + sb1];
                }
                #pragma unroll
                for (int mt = 0; mt < 2; mt++) {
                    uint32_t a[4];
                    int r0 = px0 + mt * 16 + g + qx;
                    a[0] = AsU[r0 * 32 + sa0];
                    a[1] = AsU[(r0 + 8) * 32 + sa0];
                    a[2] = AsU[r0 * 32 + sa1];
                    a[3] = AsU[(r0 + 8) * 32 + sa1];
                    #pragma unroll
                    for (int nt = 0; nt < 2; nt++)
                        mma16(C2[mt][nt], a, bb[nt * 2], bb[nt * 2 + 1]);
                }
            }
        }
        __syncthreads();
    }
    // stage C2 -> smem [n][132 stride] (fp32 overlay; 14.3KB fits A region)
    #pragma unroll
    for (int mt = 0; mt < 2; mt++)
        #pragma unroll
        for (int nt = 0; nt < 2; nt++) {
            int n = (nh * 2 + nt) * 8 + 2 * t4;
            int px = px0 + mt * 16 + g;
            if (n < 27)     { Cst[n * 132 + px]       = C2[mt][nt][0];
                              Cst[n * 132 + px + 8]   = C2[mt][nt][2]; }
            if (n + 1 < 27) { Cst[(n + 1) * 132 + px]     = C2[mt][nt][1];
                              Cst[(n + 1) * 132 + px + 8] = C2[mt][nt][3]; }
        }
    __syncthreads();

    // ============ Offsets epilogue: tables (swt as half4, sidx packed) ========
    for (int task = tid; task < 1152; task += 256) {
        int px = task / 9, n = task - px * 9;
        float offx = Cst[n * 132 + px]        + bp[n];
        float offy = Cst[(9 + n) * 132 + px]  + bp[9 + n];
        float mz   = Cst[(18 + n) * 132 + px] + bm[n];
        float mm = 1.0f / (1.0f + __expf(-mz));
        int i = n / 3, jj = n % 3;
        float p_x = (float)(h + i) + offx;
        float p_y = (float)(px + jj) + offy;
        float fx = floorf(p_x), fy = floorf(p_y);
        float qltx = fminf(fmaxf(fx,       0.f), 129.f);
        float qlty = fminf(fmaxf(fy,       0.f), 129.f);
        float qrbx = fminf(fmaxf(fx + 1.f, 0.f), 129.f);
        float qrby = fminf(fmaxf(fy + 1.f, 0.f), 129.f);
        float pcx  = fminf(fmaxf(p_x, 0.f), 129.f);
        float pcy  = fminf(fmaxf(p_y, 0.f), 129.f);
        float glt = (1.f + (qltx - pcx)) * (1.f + (qlty - pcy));
        float grb = (1.f - (qrbx - pcx)) * (1.f - (qrby - pcy));
        float glb = (1.f + (qltx - pcx)) * (1.f - (qrby - pcy));
        float grt = (1.f - (qrbx - pcx)) * (1.f + (qlty - pcy));
        int iltx = (int)qltx, ilty = (int)qlty;
        int irbx = (int)qrbx, irby = (int)qrby;
        int base = (iltx * Wp + ilty) * Cc;
        int pack = base | ((irbx - iltx) << 24) | ((irby - ilty) << 25);
        __half2 h01 = __floats2half2_rn(glt * mm, grb * mm);
        __half2 h23 = __floats2half2_rn(glb * mm, grt * mm);
        uint2 pk;
        pk.x = *(uint32_t*)&h01;
        pk.y = *(uint32_t*)&h23;
        sidx[px * 9 + n] = pack;
        swtH[px * 9 + n] = pk;
    }
    __syncthreads();

    // ============ Stage 5: sample + GEMM (M=128,N=64,K=9x64) ============
    float C5[2][4][4];
    #pragma unroll
    for (int mt = 0; mt < 2; mt++)
        #pragma unroll
        for (int nt = 0; nt < 4; nt++)
            #pragma unroll
            for (int r = 0; r < 4; r++) C5[mt][nt][r] = 0.f;

    const int n0 = nh * 32;
    const int halfsel = lane >> 4;       // which px of the pair
    const int c4h = (lane & 15) * 4;     // channel quad (halves)
    const int u0  = (lane & 15) * 2;     // half2-unit index

    for (int n = 0; n < 9; n++) {
        // B tile via cp.async: 8192 B = 512 x 16B (2 per thread)
        #pragma unroll
        for (int r = 0; r < 2; r++) {
            int f = r * 256 + tid;
            cp16(smbB5 + f * 16, g_wb5h + n * 2048 + f * 4);
        }
        asm volatile("cp.async.commit_group;");
        // A tile: fp16 bilinear samples (2 px per warp-iteration)
        #pragma unroll
        for (int k = 0; k < 8; k++) {
            int px = warp * 16 + k * 2 + halfsel;
            int si = sidx[px * 9 + n];
            uint2 pk = swtH[px * 9 + n];
            __half2 hw01 = *(__half2*)&pk.x;
            __half2 hw23 = *(__half2*)&pk.y;
            __half2 wlt = __low2half2(hw01), wrb = __high2half2(hw01);
            __half2 wlb = __low2half2(hw23), wrt = __high2half2(hw23);
            int base = (si & 0xFFFFFF) + c4h;
            int dx = (si & (1 << 24)) ? (Wp * Cc) : 0;
            int dy = (si & (1 << 25)) ? Cc : 0;
            uint2 q0 = *(const uint2*)(xpb + base);
            uint2 q1 = *(const uint2*)(xpb + base + dx + dy);
            uint2 q2 = *(const uint2*)(xpb + base + dy);
            uint2 q3 = *(const uint2*)(xpb + base + dx);
            __half2 v0 = __hfma2(wlt, *(__half2*)&q0.x,
                         __hfma2(wrb, *(__half2*)&q1.x,
                         __hfma2(wlb, *(__half2*)&q2.x,
                         __hmul2(wrt, *(__half2*)&q3.x))));
            __half2 v1 = __hfma2(wlt, *(__half2*)&q0.y,
                         __hfma2(wrb, *(__half2*)&q1.y,
                         __hfma2(wlb, *(__half2*)&q2.y,
                         __hmul2(wrt, *(__half2*)&q3.y))));
            uint2 ov;
            ov.x = *(uint32_t*)&v0;
            ov.y = *(uint32_t*)&v1;
            *(uint2*)(sm + SM_A + px * 128 + ((u0 ^ ((px & 7) << 2)) << 2)) = ov;
        }
        asm volatile("cp.async.wait_group 0;");
        __syncthreads();
        #pragma unroll
        for (int ks = 0; ks < 4; ks++) {
            const int k0 = ks * 8;
            const int sc0 = (k0 + t4) ^ (g << 2);
            const int sc1 = (k0 + t4 + 4) ^ (g << 2);
            uint32_t bb[8];
            #pragma unroll
            for (int nt = 0; nt < 4; nt++) {
                int nn = n0 + nt * 8 + g;
                bb[nt * 2]     = B5U[nn * 32 + sc0];
                bb[nt * 2 + 1] = B5U[nn * 32 + sc1];
            }
            #pragma unroll
            for (int mt = 0; mt < 2; mt++) {
                uint32_t a[4];
                int r0 = px0 + mt * 16 + g;
                a[0] = AsU[r0 * 32 + sc0];
                a[1] = AsU[(r0 + 8) * 32 + sc0];
                a[2] = AsU[r0 * 32 + sc1];
                a[3] = AsU[(r0 + 8) * 32 + sc1];
                #pragma unroll
                for (int nt = 0; nt < 4; nt++)
                    mma16(C5[mt][nt], a, bb[nt * 2], bb[nt * 2 + 1]);
            }
        }
        __syncthreads();
    }

    // stage C5 -> smem [o][128 stride] (fp32 overlay across A+B2+B5 regions)
    #pragma unroll
    for (int mt = 0; mt < 2; mt++)
        #pragma unroll
        for (int nt = 0; nt < 4; nt++) {
            int o = n0 + nt * 8 + 2 * t4;
            int px = px0 + mt * 16 + g;
            Cst[o * 128 + px]           = C5[mt][nt][0];
            Cst[(o + 1) * 128 + px]     = C5[mt][nt][1];
            Cst[o * 128 + px + 8]       = C5[mt][nt][2];
            Cst[(o + 1) * 128 + px + 8] = C5[mt][nt][3];
        }
    __syncthreads();

    // coalesced NCHW store
    float* __restrict__ ob = out + (b * Oc * Hc + h) * Wc;
    #pragma unroll
    for (int r = 0; r < 32; r++) {
        int f = r * 256 + tid;
        int o = f >> 7, px = f & 127;
        ob[o * (Hc * Wc) + px] = Cst[o * 128 + px];
    }
}

// ---------------------------------------------------------------------------
extern "C" void kernel_launch(void* const* d_in, const int* in_sizes, int n_in,
                              void* d_out, int out_size) {
    const float* x      = (const float*)d_in[0];
    const float* w_p    = (const float*)d_in[1];
    const float* b_p    = (const float*)d_in[2];
    const float* w_m    = (const float*)d_in[3];
    const float* b_m    = (const float*)d_in[4];
    const float* w_conv = (const float*)d_in[5];
    float* out = (float*)d_out;

    cudaFuncSetAttribute(deform_kernel,
                         cudaFuncAttributeMaxDynamicSharedMemorySize, SM_TOTAL);

    prep_kernel<<<516 + 4096, 256>>>(x, w_p, w_m, w_conv);
    deform_kernel<<<dim3(Hc, Bc), 256, SM_TOTAL>>>(b_p, b_m, out);
}

// round 16
// speedup vs baseline: 1.6768x; 1.1038x over previous
#include <cuda_runtime.h>
#include <cuda_fp16.h>
#include <cstdint>

#define Bc 4
#define Cc 64
#define Hc 128
#define Wc 128
#define Oc 64
#define Hp 130
#define Wp 130

// Device scratch (no allocation allowed)
__device__ __half   g_xph[Bc * Hp * Wp * Cc];  // padded NHWC x, fp16 (~8.3 MiB)
__device__ uint32_t g_wb2h[9 * 32 * 32];       // stage-2 B: [q][n 32][u 32] half2, swizzled
__device__ uint32_t g_wb5h[9 * 64 * 32];       // stage-5 B: [n][o 64][u 32] half2, swizzled

__device__ __forceinline__ uint32_t smem_u32(const void* p) {
    uint32_t a;
    asm("{ .reg .u64 t; cvta.to.shared.u64 t, %1; cvt.u32.u64 %0, t; }" : "=r"(a) : "l"(p));
    return a;
}
__device__ __forceinline__ void cp16(uint32_t dst, const void* src) {
    asm volatile("cp.async.ca.shared.global [%0], [%1], 16;" :: "r"(dst), "l"(src));
}

// m16n8k16 fp16 MMA, fp32 accumulate
__device__ __forceinline__ void mma16(float* c, const uint32_t* a, uint32_t b0, uint32_t b1) {
    asm volatile("mma.sync.aligned.m16n8k16.row.col.f32.f16.f16.f32 "
        "{%0,%1,%2,%3}, {%4,%5,%6,%7}, {%8,%9}, {%0,%1,%2,%3};"
        : "+f"(c[0]), "+f"(c[1]), "+f"(c[2]), "+f"(c[3])
        : "r"(a[0]), "r"(a[1]), "r"(a[2]), "r"(a[3]), "r"(b0), "r"(b1));
}

// smem layout (bytes). C staging (fp32) overlays A+B2+B5 regions.
#define SM_A     0          /* stage2 A row 130x128B=16640 (pad 16896); stage5 A 16384 */
#define SM_B2    16896      /* 3 x 4096 */
#define SM_B5    29184      /* 8192 (64 o-rows x 128B) */
#define SM_SWT   37376      /* uint2[1152] = 9216 */
#define SM_SIDX  46592      /* int[1152] = 4608 */
#define SM_TOTAL 51200

// ---------------------------------------------------------------------------
// Fused prep: border zero + weight transposes (fp16 pack) + NCHW->NHWC fp16
// ---------------------------------------------------------------------------
__global__ __launch_bounds__(256) void prep_kernel(
    const float* __restrict__ x,
    const float* __restrict__ wp,
    const float* __restrict__ wm,
    const float* __restrict__ wc) {
    if (blockIdx.x < 516) {
        int i = blockIdx.x * 256 + threadIdx.x;
        const int per = (2 * 130 + 2 * 128) * 64;  // 33024
        if (i < Bc * per) {
            int b = i / per, r = i % per;
            int base = b * Hp * Wp * Cc;
            __half z = __float2half(0.f);
            if (r < 130 * 64)            g_xph[base + r] = z;
            else if (r < 2 * 130 * 64)   g_xph[base + 129 * Wp * Cc + (r - 130 * 64)] = z;
            else {
                int t = r - 2 * 130 * 64;
                int which = t / (128 * 64);
                int u = t % (128 * 64);
                int rr = u / 64, c = u % 64;
                int w = which ? 129 : 0;
                g_xph[base + (rr + 1) * Wp * Cc + w * Cc + c] = z;
            }
        }
        if (i < 9 * 32 * 32) {
            int q = i >> 10, rem = i & 1023, n = rem >> 5, u = rem & 31;
            int c0 = 2 * u, c1 = 2 * u + 1;
            float v0 = 0.f, v1 = 0.f;
            if (n < 18)      { v0 = wp[n * 576 + c0 * 9 + q]; v1 = wp[n * 576 + c1 * 9 + q]; }
            else if (n < 27) { v0 = wm[(n - 18) * 576 + c0 * 9 + q]; v1 = wm[(n - 18) * 576 + c1 * 9 + q]; }
            __half2 hv = __floats2half2_rn(v0, v1);
            g_wb2h[q * 1024 + n * 32 + (u ^ ((n & 7) << 2))] = *(uint32_t*)&hv;
        }
        if (i < 9 * 64 * 32) {
            int n = i >> 11, rem = i & 2047, o = rem >> 5, u = rem & 31;
            float v0 = wc[o * 576 + (2 * u) * 9 + n];
            float v1 = wc[o * 576 + (2 * u + 1) * 9 + n];
            __half2 hv = __floats2half2_rn(v0, v1);
            g_wb5h[n * 2048 + o * 32 + (u ^ ((o & 7) << 2))] = *(uint32_t*)&hv;
        }
    } else {
        int bid = blockIdx.x - 516;
        int wblk = bid & 3, h = (bid >> 2) & 127, z = bid >> 9;
        int b = z >> 1, cblk = z & 1;
        __shared__ float tile[32][33];
        int l = threadIdx.x;
        int tx = l & 31, ty = l >> 5;
        #pragma unroll
        for (int r = 0; r < 4; r++) {
            int c = ty + r * 8;
            tile[c][tx] = x[((b * Cc + cblk * 32 + c) * Hc + h) * Wc + wblk * 32 + tx];
        }
        __syncthreads();
        int j = l & 7, w2 = l >> 3;
        __half2 h0 = __floats2half2_rn(tile[j * 4 + 0][w2], tile[j * 4 + 1][w2]);
        __half2 h1 = __floats2half2_rn(tile[j * 4 + 2][w2], tile[j * 4 + 3][w2]);
        uint2 v;
        v.x = *(uint32_t*)&h0;
        v.y = *(uint32_t*)&h1;
        *(uint2*)(g_xph + ((b * Hp + (h + 1)) * Wp + (wblk * 32 + w2 + 1)) * Cc
                  + cblk * 32 + j * 4) = v;
    }
}

// ---------------------------------------------------------------------------
// Main fused kernel: 1 block = one (b,h) row of 128 pixels, 512 threads
// 16 warps. Stage-2 warp tile: 16px x 16n. Stage-5 warp tile: 16px x 32n.
// ---------------------------------------------------------------------------
__global__ __launch_bounds__(512, 2) void deform_kernel(
    const float* __restrict__ bp, const float* __restrict__ bm,
    float* __restrict__ out) {

    extern __shared__ char sm[];
    uint32_t* AsU  = (uint32_t*)(sm + SM_A);   // half2-unit view
    uint32_t* B2U  = (uint32_t*)(sm + SM_B2);
    uint32_t* B5U  = (uint32_t*)(sm + SM_B5);
    uint2*    swtH = (uint2*)(sm + SM_SWT);
    int*      sidx = (int*)(sm + SM_SIDX);
    float*    Cst  = (float*)(sm + SM_A);      // fp32 staging overlay

    const uint32_t smbA  = smem_u32(sm) + SM_A;
    const uint32_t smbB2 = smem_u32(sm) + SM_B2;
    const uint32_t smbB5 = smem_u32(sm) + SM_B5;
    const int tid = threadIdx.x;
    const int warp = tid >> 5, lane = tid & 31;
    const int g = lane >> 2, t4 = lane & 3;
    const int mgw = warp >> 1, nh = warp & 1;
    const int px0 = mgw * 16;
    const int h = blockIdx.x, b = blockIdx.y;
    const __half* __restrict__ xpb = g_xph + b * (Hp * Wp * Cc);

    // ================= Stage 2: offset/mod conv GEMM (M=128,N=32,K=9x64) =====
    float C2[2][4];
    #pragma unroll
    for (int nt = 0; nt < 2; nt++)
        #pragma unroll
        for (int r = 0; r < 4; r++) C2[nt][r] = 0.f;

    for (int qy = 0; qy < 3; qy++) {
        const __half* src = xpb + (h + qy) * Wp * Cc;
        // A row: 130 px x 128B = 1040 x 16B
        #pragma unroll
        for (int r = 0; r < 3; r++) {
            int f = r * 512 + tid;
            if (f < 1040) {
                int px = f >> 3, ug = f & 7;
                cp16(smbA + px * 128 + ((ug ^ (px & 7)) << 4), src + px * 64 + ug * 8);
            }
        }
        // 3 B tiles: 768 x 16B
        {
            int f = tid;
            cp16(smbB2 + f * 16, g_wb2h + qy * 3 * 1024 + f * 4);
            f = 512 + tid;
            if (f < 768) cp16(smbB2 + f * 16, g_wb2h + qy * 3 * 1024 + f * 4);
        }
        asm volatile("cp.async.commit_group;");
        asm volatile("cp.async.wait_group 0;");
        __syncthreads();
        #pragma unroll
        for (int qx = 0; qx < 3; qx++) {
            const int gq = (g + qx) & 7;
            #pragma unroll
            for (int ks = 0; ks < 4; ks++) {
                const int k0 = ks * 8;
                const int sa0 = (k0 + t4) ^ (gq << 2);
                const int sa1 = (k0 + t4 + 4) ^ (gq << 2);
                const int sb0 = (k0 + t4) ^ (g << 2);
                const int sb1 = (k0 + t4 + 4) ^ (g << 2);
                uint32_t a[4];
                int r0 = px0 + g + qx;
                a[0] = AsU[r0 * 32 + sa0];
                a[1] = AsU[(r0 + 8) * 32 + sa0];
                a[2] = AsU[r0 * 32 + sa1];
                a[3] = AsU[(r0 + 8) * 32 + sa1];
                #pragma unroll
                for (int nt = 0; nt < 2; nt++) {
                    int n = nh * 16 + nt * 8 + g;
                    mma16(C2[nt], a, B2U[qx * 1024 + n * 32 + sb0],
                                     B2U[qx * 1024 + n * 32 + sb1]);
                }
            }
        }
        __syncthreads();
    }
    // stage C2 -> smem [n][132 stride] (fp32 overlay; 14.3KB fits A region)
    #pragma unroll
    for (int nt = 0; nt < 2; nt++) {
        int n = nh * 16 + nt * 8 + 2 * t4;
        int px = px0 + g;
        if (n < 27)     { Cst[n * 132 + px]       = C2[nt][0];
                          Cst[n * 132 + px + 8]   = C2[nt][2]; }
        if (n + 1 < 27) { Cst[(n + 1) * 132 + px]     = C2[nt][1];
                          Cst[(n + 1) * 132 + px + 8] = C2[nt][3]; }
    }
    __syncthreads();

    // ============ Offsets epilogue: tables (swt as half4, sidx packed) ========
    for (int task = tid; task < 1152; task += 512) {
        int px = task / 9, n = task - px * 9;
        float offx = Cst[n * 132 + px]        + bp[n];
        float offy = Cst[(9 + n) * 132 + px]  + bp[9 + n];
        float mz   = Cst[(18 + n) * 132 + px] + bm[n];
        float mm = 1.0f / (1.0f + __expf(-mz));
        int i = n / 3, jj = n % 3;
        float p_x = (float)(h + i) + offx;
        float p_y = (float)(px + jj) + offy;
        float fx = floorf(p_x), fy = floorf(p_y);
        float qltx = fminf(fmaxf(fx,       0.f), 129.f);
        float qlty = fminf(fmaxf(fy,       0.f), 129.f);
        float qrbx = fminf(fmaxf(fx + 1.f, 0.f), 129.f);
        float qrby = fminf(fmaxf(fy + 1.f, 0.f), 129.f);
        float pcx  = fminf(fmaxf(p_x, 0.f), 129.f);
        float pcy  = fminf(fmaxf(p_y, 0.f), 129.f);
        float glt = (1.f + (qltx - pcx)) * (1.f + (qlty - pcy));
        float grb = (1.f - (qrbx - pcx)) * (1.f - (qrby - pcy));
        float glb = (1.f + (qltx - pcx)) * (1.f - (qrby - pcy));
        float grt = (1.f - (qrbx - pcx)) * (1.f + (qlty - pcy));
        int iltx = (int)qltx, ilty = (int)qlty;
        int irbx = (int)qrbx, irby = (int)qrby;
        int base = (iltx * Wp + ilty) * Cc;
        int pack = base | ((irbx - iltx) << 24) | ((irby - ilty) << 25);
        __half2 h01 = __floats2half2_rn(glt * mm, grb * mm);
        __half2 h23 = __floats2half2_rn(glb * mm, grt * mm);
        uint2 pk;
        pk.x = *(uint32_t*)&h01;
        pk.y = *(uint32_t*)&h23;
        sidx[px * 9 + n] = pack;
        swtH[px * 9 + n] = pk;
    }
    __syncthreads();

    // ============ Stage 5: sample + GEMM (M=128,N=64,K=9x64) ============
    float C5[4][4];
    #pragma unroll
    for (int nt = 0; nt < 4; nt++)
        #pragma unroll
        for (int r = 0; r < 4; r++) C5[nt][r] = 0.f;

    const int n0 = nh * 32;
    const int spx0 = warp * 8;            // sampling px range per warp
    const int psel = lane >> 3;           // px within group of 4
    const int c8h  = (lane & 7) * 8;      // channel offset (halves)
    const int u0   = (lane & 7) * 4;      // half2-unit index

    for (int n = 0; n < 9; n++) {
        // B tile via cp.async: 8192 B = 512 x 16B (1 per thread)
        cp16(smbB5 + tid * 16, g_wb5h + n * 2048 + tid * 4);
        asm volatile("cp.async.commit_group;");
        // A tile: fp16 bilinear samples, LDG.128 taps (4 px per warp-pass)
        #pragma unroll
        for (int k = 0; k < 2; k++) {
            int px = spx0 + k * 4 + psel;
            int si = sidx[px * 9 + n];
            uint2 pk = swtH[px * 9 + n];
            __half2 hw01 = *(__half2*)&pk.x;
            __half2 hw23 = *(__half2*)&pk.y;
            __half2 wlt = __low2half2(hw01), wrb = __high2half2(hw01);
            __half2 wlb = __low2half2(hw23), wrt = __high2half2(hw23);
            int base = (si & 0xFFFFFF) + c8h;
            int dx = (si & (1 << 24)) ? (Wp * Cc) : 0;
            int dy = (si & (1 << 25)) ? Cc : 0;
            uint4 q0 = *(const uint4*)(xpb + base);
            uint4 q1 = *(const uint4*)(xpb + base + dx + dy);
            uint4 q2 = *(const uint4*)(xpb + base + dy);
            uint4 q3 = *(const uint4*)(xpb + base + dx);
            uint4 ov;
            #pragma unroll
            for (int j = 0; j < 4; j++) {
                uint32_t a0 = (&q0.x)[j], a1 = (&q1.x)[j];
                uint32_t a2 = (&q2.x)[j], a3 = (&q3.x)[j];
                __half2 v = __hfma2(wlt, *(__half2*)&a0,
                            __hfma2(wrb, *(__half2*)&a1,
                            __hfma2(wlb, *(__half2*)&a2,
                            __hmul2(wrt, *(__half2*)&a3))));
                (&ov.x)[j] = *(uint32_t*)&v;
            }
            *(uint4*)(sm + SM_A + px * 128 + ((u0 ^ ((px & 7) << 2)) << 2)) = ov;
        }
        asm volatile("cp.async.wait_group 0;");
        __syncthreads();
        #pragma unroll
        for (int ks = 0; ks < 4; ks++) {
            const int k0 = ks * 8;
            const int sc0 = (k0 + t4) ^ (g << 2);
            const int sc1 = (k0 + t4 + 4) ^ (g << 2);
            uint32_t a[4];
            int r0 = px0 + g;
            a[0] = AsU[r0 * 32 + sc0];
            a[1] = AsU[(r0 + 8) * 32 + sc0];
            a[2] = AsU[r0 * 32 + sc1];
            a[3] = AsU[(r0 + 8) * 32 + sc1];
            #pragma unroll
            for (int nt = 0; nt < 4; nt++) {
                int nn = n0 + nt * 8 + g;
                mma16(C5[nt], a, B5U[nn * 32 + sc0], B5U[nn * 32 + sc1]);
            }
        }
        __syncthreads();
    }

    // stage C5 -> smem [o][128 stride] (fp32 overlay across A+B2+B5 regions)
    #pragma unroll
    for (int nt = 0; nt < 4; nt++) {
        int o = n0 + nt * 8 + 2 * t4;
        int px = px0 + g;
        Cst[o * 128 + px]           = C5[nt][0];
        Cst[(o + 1) * 128 + px]     = C5[nt][1];
        Cst[o * 128 + px + 8]       = C5[nt][2];
        Cst[(o + 1) * 128 + px + 8] = C5[nt][3];
    }
    __syncthreads();

    // coalesced NCHW store
    float* __restrict__ ob = out + (b * Oc * Hc + h) * Wc;
    #pragma unroll
    for (int r = 0; r < 16; r++) {
        int f = r * 512 + tid;
        int o = f >> 7, px = f & 127;
        ob[o * (Hc * Wc) + px] = Cst[o * 128 + px];
    }
}

// ---------------------------------------------------------------------------
extern "C" void kernel_launch(void* const* d_in, const int* in_sizes, int n_in,
                              void* d_out, int out_size) {
    const float* x      = (const float*)d_in[0];
    const float* w_p    = (const float*)d_in[1];
    const float* b_p    = (const float*)d_in[2];
    const float* w_m    = (const float*)d_in[3];
    const float* b_m    = (const float*)d_in[4];
    const float* w_conv = (const float*)d_in[5];
    float* out = (float*)d_out;

    cudaFuncSetAttribute(deform_kernel,
                         cudaFuncAttributeMaxDynamicSharedMemorySize, SM_TOTAL);

    prep_kernel<<<516 + 4096, 256>>>(x, w_p, w_m, w_conv);
    deform_kernel<<<dim3(Hc, Bc), 512, SM_TOTAL>>>(b_p, b_m, out);
}

// round 17
// speedup vs baseline: 1.7493x; 1.0432x over previous
#include <cuda_runtime.h>
#include <cuda_fp16.h>
#include <cstdint>

#define Bc 4
#define Cc 64
#define Hc 128
#define Wc 128
#define Oc 64
#define Hp 130
#define Wp 130

// Device scratch (no allocation allowed)
__device__ __half   g_xph[Bc * Hp * Wp * Cc];  // padded NHWC x, fp16 (~8.3 MiB)
__device__ uint32_t g_wb2h[9 * 32 * 32];       // stage-2 B: [q][n 32][u 32] half2, swizzled
__device__ uint32_t g_wb5h[9 * 64 * 32];       // stage-5 B: [n][o 64][u 32] half2, swizzled

__device__ __forceinline__ uint32_t smem_u32(const void* p) {
    uint32_t a;
    asm("{ .reg .u64 t; cvta.to.shared.u64 t, %1; cvt.u32.u64 %0, t; }" : "=r"(a) : "l"(p));
    return a;
}
__device__ __forceinline__ void cp16(uint32_t dst, const void* src) {
    asm volatile("cp.async.ca.shared.global [%0], [%1], 16;" :: "r"(dst), "l"(src));
}

// m16n8k16 fp16 MMA, fp32 accumulate
__device__ __forceinline__ void mma16(float* c, const uint32_t* a, uint32_t b0, uint32_t b1) {
    asm volatile("mma.sync.aligned.m16n8k16.row.col.f32.f16.f16.f32 "
        "{%0,%1,%2,%3}, {%4,%5,%6,%7}, {%8,%9}, {%0,%1,%2,%3};"
        : "+f"(c[0]), "+f"(c[1]), "+f"(c[2]), "+f"(c[3])
        : "r"(a[0]), "r"(a[1]), "r"(a[2]), "r"(a[3]), "r"(b0), "r"(b1));
}
__device__ __forceinline__ void ldsm4(uint32_t& r0, uint32_t& r1, uint32_t& r2,
                                      uint32_t& r3, uint32_t addr) {
    asm volatile("ldmatrix.sync.aligned.m8n8.x4.shared.b16 {%0,%1,%2,%3}, [%4];"
        : "=r"(r0), "=r"(r1), "=r"(r2), "=r"(r3) : "r"(addr));
}

// smem layout (bytes). C staging (fp32) overlays A+B2+B5 regions.
#define SM_A     0          /* stage2 A row 130x128B=16640 (pad 16896); stage5 A 16384 */
#define SM_B2    16896      /* 3 x 4096 */
#define SM_B5    29184      /* 8192 (64 o-rows x 128B) */
#define SM_SWT   37376      /* uint2[1152] = 9216 */
#define SM_SIDX  46592      /* int[1152] = 4608 */
#define SM_TOTAL 51200

// ---------------------------------------------------------------------------
// Fused prep: border zero + weight transposes (fp16 pack) + NCHW->NHWC fp16
// ---------------------------------------------------------------------------
__global__ __launch_bounds__(256) void prep_kernel(
    const float* __restrict__ x,
    const float* __restrict__ wp,
    const float* __restrict__ wm,
    const float* __restrict__ wc) {
    if (blockIdx.x < 516) {
        int i = blockIdx.x * 256 + threadIdx.x;
        const int per = (2 * 130 + 2 * 128) * 64;  // 33024
        if (i < Bc * per) {
            int b = i / per, r = i % per;
            int base = b * Hp * Wp * Cc;
            __half z = __float2half(0.f);
            if (r < 130 * 64)            g_xph[base + r] = z;
            else if (r < 2 * 130 * 64)   g_xph[base + 129 * Wp * Cc + (r - 130 * 64)] = z;
            else {
                int t = r - 2 * 130 * 64;
                int which = t / (128 * 64);
                int u = t % (128 * 64);
                int rr = u / 64, c = u % 64;
                int w = which ? 129 : 0;
                g_xph[base + (rr + 1) * Wp * Cc + w * Cc + c] = z;
            }
        }
        if (i < 9 * 32 * 32) {
            int q = i >> 10, rem = i & 1023, n = rem >> 5, u = rem & 31;
            int c0 = 2 * u, c1 = 2 * u + 1;
            float v0 = 0.f, v1 = 0.f;
            if (n < 18)      { v0 = wp[n * 576 + c0 * 9 + q]; v1 = wp[n * 576 + c1 * 9 + q]; }
            else if (n < 27) { v0 = wm[(n - 18) * 576 + c0 * 9 + q]; v1 = wm[(n - 18) * 576 + c1 * 9 + q]; }
            __half2 hv = __floats2half2_rn(v0, v1);
            g_wb2h[q * 1024 + n * 32 + (u ^ ((n & 7) << 2))] = *(uint32_t*)&hv;
        }
        if (i < 9 * 64 * 32) {
            int n = i >> 11, rem = i & 2047, o = rem >> 5, u = rem & 31;
            float v0 = wc[o * 576 + (2 * u) * 9 + n];
            float v1 = wc[o * 576 + (2 * u + 1) * 9 + n];
            __half2 hv = __floats2half2_rn(v0, v1);
            g_wb5h[n * 2048 + o * 32 + (u ^ ((o & 7) << 2))] = *(uint32_t*)&hv;
        }
    } else {
        int bid = blockIdx.x - 516;
        int wblk = bid & 3, h = (bid >> 2) & 127, z = bid >> 9;
        int b = z >> 1, cblk = z & 1;
        __shared__ float tile[32][33];
        int l = threadIdx.x;
        int tx = l & 31, ty = l >> 5;
        #pragma unroll
        for (int r = 0; r < 4; r++) {
            int c = ty + r * 8;
            tile[c][tx] = x[((b * Cc + cblk * 32 + c) * Hc + h) * Wc + wblk * 32 + tx];
        }
        __syncthreads();
        int j = l & 7, w2 = l >> 3;
        __half2 h0 = __floats2half2_rn(tile[j * 4 + 0][w2], tile[j * 4 + 1][w2]);
        __half2 h1 = __floats2half2_rn(tile[j * 4 + 2][w2], tile[j * 4 + 3][w2]);
        uint2 v;
        v.x = *(uint32_t*)&h0;
        v.y = *(uint32_t*)&h1;
        *(uint2*)(g_xph + ((b * Hp + (h + 1)) * Wp + (wblk * 32 + w2 + 1)) * Cc
                  + cblk * 32 + j * 4) = v;
    }
}

// ---------------------------------------------------------------------------
// Main fused kernel: 1 block = one (b,h) row of 128 pixels, 512 threads
// 16 warps. Stage-2 warp tile: 16px x 16n. Stage-5 warp tile: 16px x 32n.
// Fragment loads via ldmatrix.x4 on the XOR-16B swizzled layout.
// ---------------------------------------------------------------------------
__global__ __launch_bounds__(512, 2) void deform_kernel(
    const float* __restrict__ bp, const float* __restrict__ bm,
    float* __restrict__ out) {

    extern __shared__ char sm[];
    uint2*    swtH = (uint2*)(sm + SM_SWT);
    int*      sidx = (int*)(sm + SM_SIDX);
    float*    Cst  = (float*)(sm + SM_A);      // fp32 staging overlay

    const uint32_t smbA  = smem_u32(sm) + SM_A;
    const uint32_t smbB2 = smem_u32(sm) + SM_B2;
    const uint32_t smbB5 = smem_u32(sm) + SM_B5;
    const int tid = threadIdx.x;
    const int warp = tid >> 5, lane = tid & 31;
    const int g = lane >> 2, t4 = lane & 3;
    const int mgw = warp >> 1, nh = warp & 1;
    const int px0 = mgw * 16;
    const int h = blockIdx.x, b = blockIdx.y;
    const __half* __restrict__ xpb = g_xph + b * (Hp * Wp * Cc);

    // ldmatrix lane constants
    const int la_r = lane & 15, la_c = lane >> 4;            // A: row, k-chunk
    const int lb_roff = ((lane >> 4) << 3) | (lane & 7);     // B: row-in-16
    const int lb_c = (lane >> 3) & 1;                        // B: k-chunk
    const int bXor = lb_roff & 7;

    // ================= Stage 2: offset/mod conv GEMM (M=128,N=32,K=9x64) =====
    float C2[2][4];
    #pragma unroll
    for (int nt = 0; nt < 2; nt++)
        #pragma unroll
        for (int r = 0; r < 4; r++) C2[nt][r] = 0.f;

    for (int qy = 0; qy < 3; qy++) {
        const __half* src = xpb + (h + qy) * Wp * Cc;
        // A row: 130 px x 128B = 1040 x 16B
        #pragma unroll
        for (int r = 0; r < 3; r++) {
            int f = r * 512 + tid;
            if (f < 1040) {
                int px = f >> 3, ug = f & 7;
                cp16(smbA + px * 128 + ((ug ^ (px & 7)) << 4), src + px * 64 + ug * 8);
            }
        }
        // 3 B tiles: 768 x 16B
        {
            int f = tid;
            cp16(smbB2 + f * 16, g_wb2h + qy * 3 * 1024 + f * 4);
            f = 512 + tid;
            if (f < 768) cp16(smbB2 + f * 16, g_wb2h + qy * 3 * 1024 + f * 4);
        }
        asm volatile("cp.async.commit_group;");
        asm volatile("cp.async.wait_group 0;");
        __syncthreads();
        #pragma unroll
        for (int qx = 0; qx < 3; qx++) {
            const uint32_t aBase = smbA + (px0 + la_r + qx) * 128;
            const int aXor = (la_r + qx) & 7;
            const uint32_t bBase = smbB2 + qx * 4096 + (nh * 16 + lb_roff) * 128;
            #pragma unroll
            for (int ks = 0; ks < 4; ks++) {
                uint32_t a[4], bb[4];
                ldsm4(a[0], a[1], a[2], a[3],
                      aBase + ((((ks << 1) + la_c) ^ aXor) << 4));
                ldsm4(bb[0], bb[1], bb[2], bb[3],
                      bBase + ((((ks << 1) + lb_c) ^ bXor) << 4));
                mma16(C2[0], a, bb[0], bb[1]);
                mma16(C2[1], a, bb[2], bb[3]);
            }
        }
        __syncthreads();
    }
    // stage C2 -> smem [n][132 stride] (fp32 overlay; 14.3KB fits A region)
    #pragma unroll
    for (int nt = 0; nt < 2; nt++) {
        int n = nh * 16 + nt * 8 + 2 * t4;
        int px = px0 + g;
        if (n < 27)     { Cst[n * 132 + px]       = C2[nt][0];
                          Cst[n * 132 + px + 8]   = C2[nt][2]; }
        if (n + 1 < 27) { Cst[(n + 1) * 132 + px]     = C2[nt][1];
                          Cst[(n + 1) * 132 + px + 8] = C2[nt][3]; }
    }
    __syncthreads();

    // ============ Offsets epilogue: tables (swt as half4, sidx packed) ========
    for (int task = tid; task < 1152; task += 512) {
        int px = task / 9, n = task - px * 9;
        float offx = Cst[n * 132 + px]        + bp[n];
        float offy = Cst[(9 + n) * 132 + px]  + bp[9 + n];
        float mz   = Cst[(18 + n) * 132 + px] + bm[n];
        float mm = 1.0f / (1.0f + __expf(-mz));
        int i = n / 3, jj = n % 3;
        float p_x = (float)(h + i) + offx;
        float p_y = (float)(px + jj) + offy;
        float fx = floorf(p_x), fy = floorf(p_y);
        float qltx = fminf(fmaxf(fx,       0.f), 129.f);
        float qlty = fminf(fmaxf(fy,       0.f), 129.f);
        float qrbx = fminf(fmaxf(fx + 1.f, 0.f), 129.f);
        float qrby = fminf(fmaxf(fy + 1.f, 0.f), 129.f);
        float pcx  = fminf(fmaxf(p_x, 0.f), 129.f);
        float pcy  = fminf(fmaxf(p_y, 0.f), 129.f);
        float glt = (1.f + (qltx - pcx)) * (1.f + (qlty - pcy));
        float grb = (1.f - (qrbx - pcx)) * (1.f - (qrby - pcy));
        float glb = (1.f + (qltx - pcx)) * (1.f - (qrby - pcy));
        float grt = (1.f - (qrbx - pcx)) * (1.f + (qlty - pcy));
        int iltx = (int)qltx, ilty = (int)qlty;
        int irbx = (int)qrbx, irby = (int)qrby;
        int base = (iltx * Wp + ilty) * Cc;
        int pack = base | ((irbx - iltx) << 24) | ((irby - ilty) << 25);
        __half2 h01 = __floats2half2_rn(glt * mm, grb * mm);
        __half2 h23 = __floats2half2_rn(glb * mm, grt * mm);
        uint2 pk;
        pk.x = *(uint32_t*)&h01;
        pk.y = *(uint32_t*)&h23;
        sidx[px * 9 + n] = pack;
        swtH[px * 9 + n] = pk;
    }
    __syncthreads();

    // ============ Stage 5: sample + GEMM (M=128,N=64,K=9x64) ============
    float C5[4][4];
    #pragma unroll
    for (int nt = 0; nt < 4; nt++)
        #pragma unroll
        for (int r = 0; r < 4; r++) C5[nt][r] = 0.f;

    const int n0 = nh * 32;
    const int spx0 = warp * 8;            // sampling px range per warp
    const int psel = lane >> 3;           // px within group of 4
    const int c8h  = (lane & 7) * 8;      // channel offset (halves)
    const int u0   = (lane & 7) * 4;      // half2-unit index

    const uint32_t aBase5 = smbA + (px0 + la_r) * 128;
    const int aXor5 = la_r & 7;
    const uint32_t bBase50 = smbB5 + (n0 + lb_roff) * 128;
    const uint32_t bBase51 = bBase50 + 16 * 128;

    for (int n = 0; n < 9; n++) {
        // B tile via cp.async: 8192 B = 512 x 16B (1 per thread)
        cp16(smbB5 + tid * 16, g_wb5h + n * 2048 + tid * 4);
        asm volatile("cp.async.commit_group;");
        // A tile: fp16 bilinear samples, LDG.128 taps (4 px per warp-pass)
        #pragma unroll
        for (int k = 0; k < 2; k++) {
            int px = spx0 + k * 4 + psel;
            int si = sidx[px * 9 + n];
            uint2 pk = swtH[px * 9 + n];
            __half2 hw01 = *(__half2*)&pk.x;
            __half2 hw23 = *(__half2*)&pk.y;
            __half2 wlt = __low2half2(hw01), wrb = __high2half2(hw01);
            __half2 wlb = __low2half2(hw23), wrt = __high2half2(hw23);
            int base = (si & 0xFFFFFF) + c8h;
            int dx = (si & (1 << 24)) ? (Wp * Cc) : 0;
            int dy = (si & (1 << 25)) ? Cc : 0;
            uint4 q0 = *(const uint4*)(xpb + base);
            uint4 q1 = *(const uint4*)(xpb + base + dx + dy);
            uint4 q2 = *(const uint4*)(xpb + base + dy);
            uint4 q3 = *(const uint4*)(xpb + base + dx);
            uint4 ov;
            #pragma unroll
            for (int j = 0; j < 4; j++) {
                uint32_t a0 = (&q0.x)[j], a1 = (&q1.x)[j];
                uint32_t a2 = (&q2.x)[j], a3 = (&q3.x)[j];
                __half2 v = __hfma2(wlt, *(__half2*)&a0,
                            __hfma2(wrb, *(__half2*)&a1,
                            __hfma2(wlb, *(__half2*)&a2,
                            __hmul2(wrt, *(__half2*)&a3))));
                (&ov.x)[j] = *(uint32_t*)&v;
            }
            *(uint4*)(sm + SM_A + px * 128 + ((u0 ^ ((px & 7) << 2)) << 2)) = ov;
        }
        asm volatile("cp.async.wait_group 0;");
        __syncthreads();
        #pragma unroll
        for (int ks = 0; ks < 4; ks++) {
            uint32_t a[4], bb[4], bb2[4];
            ldsm4(a[0], a[1], a[2], a[3],
                  aBase5 + ((((ks << 1) + la_c) ^ aXor5) << 4));
            ldsm4(bb[0], bb[1], bb[2], bb[3],
                  bBase50 + ((((ks << 1) + lb_c) ^ bXor) << 4));
            ldsm4(bb2[0], bb2[1], bb2[2], bb2[3],
                  bBase51 + ((((ks << 1) + lb_c) ^ bXor) << 4));
            mma16(C5[0], a, bb[0], bb[1]);
            mma16(C5[1], a, bb[2], bb[3]);
            mma16(C5[2], a, bb2[0], bb2[1]);
            mma16(C5[3], a, bb2[2], bb2[3]);
        }
        __syncthreads();
    }

    // stage C5 -> smem [o][128 stride] (fp32 overlay across A+B2+B5 regions)
    #pragma unroll
    for (int nt = 0; nt < 4; nt++) {
        int o = n0 + nt * 8 + 2 * t4;
        int px = px0 + g;
        Cst[o * 128 + px]           = C5[nt][0];
        Cst[(o + 1) * 128 + px]     = C5[nt][1];
        Cst[o * 128 + px + 8]       = C5[nt][2];
        Cst[(o + 1) * 128 + px + 8] = C5[nt][3];
    }
    __syncthreads();

    // coalesced NCHW store
    float* __restrict__ ob = out + (b * Oc * Hc + h) * Wc;
    #pragma unroll
    for (int r = 0; r < 16; r++) {
        int f = r * 512 + tid;
        int o = f >> 7, px = f & 127;
        ob[o * (Hc * Wc) + px] = Cst[o * 128 + px];
    }
}

// ---------------------------------------------------------------------------
extern "C" void kernel_launch(void* const* d_in, const int* in_sizes, int n_in,
                              void* d_out, int out_size) {
    const float* x      = (const float*)d_in[0];
    const float* w_p    = (const float*)d_in[1];
    const float* b_p    = (const float*)d_in[2];
    const float* w_m    = (const float*)d_in[3];
    const float* b_m    = (const float*)d_in[4];
    const float* w_conv = (const float*)d_in[5];
    float* out = (float*)d_out;

    cudaFuncSetAttribute(deform_kernel,
                         cudaFuncAttributeMaxDynamicSharedMemorySize, SM_TOTAL);

    prep_kernel<<<516 + 4096, 256>>>(x, w_p, w_m, w_conv);
    deform_kernel<<<dim3(Hc, Bc), 512, SM_TOTAL>>>(b_p, b_m, out);
}